// round 4
// baseline (speedup 1.0000x reference)
#include <cuda_runtime.h>

#define NLAB   2047
#define NBATCH 2048
#define NTHR   256

// Compact transition tables, gathered once per launch (deterministic).
// Tup[n] = transitions[parent(n), n, :, :]  (message n -> parent)
// Tdn[n] = transitions[n, parent(n), :, :]  (message parent -> n)
// float4: x=T[cd=0][cs=0], y=T[0][1], z=T[1][0], w=T[1][1]
__device__ float4 g_Tup[2048];
__device__ float4 g_Tdn[2048];

__global__ void prep_kernel(const float* __restrict__ trans) {
    int n = blockIdx.x * blockDim.x + threadIdx.x;
    if (n >= NLAB) return;
    if (n == 0) {
        g_Tup[0] = make_float4(0.f, 0.f, 0.f, 0.f);
        g_Tdn[0] = make_float4(0.f, 0.f, 0.f, 0.f);
        return;
    }
    int p = (n - 1) >> 1;
    const float4* t4 = reinterpret_cast<const float4*>(trans);
    g_Tup[n] = t4[(size_t)p * NLAB + n];   // dst=parent, src=n
    g_Tdn[n] = t4[(size_t)n * NLAB + p];   // dst=n, src=parent
}

__device__ __forceinline__ float lse2(float u, float v) {
    float m = fmaxf(u, v);
    float d = fminf(u, v) - m;              // <= 0
    return m + __logf(1.0f + __expf(d));
}

// alpha of a parent whose two children are l and l+1, with E/A in smem
__device__ __forceinline__ void alpha_children(int l,
        const float* E0, const float* E1, const float* A0, const float* A1,
        float& a0, float& a1) {
    float xl0 = E0[l] + A0[l],     xl1 = E1[l] + A1[l];
    float xr0 = E0[l+1] + A0[l+1], xr1 = E1[l+1] + A1[l+1];
    float4 Tl = g_Tup[l], Tr = g_Tup[l+1];
    a0 = lse2(xl0 + Tl.x, xl1 + Tl.y) + lse2(xr0 + Tr.x, xr1 + Tr.y);
    a1 = lse2(xl0 + Tl.z, xl1 + Tl.w) + lse2(xr0 + Tr.z, xr1 + Tr.w);
}

// t[n] = e[n] + beta[n], given parent's t
__device__ __forceinline__ void down_t(int n, float tp0, float tp1,
                                       float e0, float e1, float& t0, float& t1) {
    float4 T = g_Tdn[n];
    t0 = e0 + lse2(tp0 + T.x, tp1 + T.y);
    t1 = e1 + lse2(tp0 + T.z, tp1 + T.w);
}

__device__ __forceinline__ void emit(float* __restrict__ orow, int n,
                                     float s0, float s1) {
    float z = lse2(s0, s1);
    orow[n]        = s0 - z;
    orow[NLAB + n] = s1 - z;
}

// smem: E for internal nodes 0..1022 (becomes t=e+beta in place on the way down)
// and A (alphas) for internal nodes. Leaves: alpha == 0, E read from global.
// 4 * 1024 * 4 B = 16 KB -> occupancy capped by regs (forced 6 CTAs/SM).
__global__ __launch_bounds__(NTHR, 6) void crf_kernel(const float* __restrict__ em,
                                                      float* __restrict__ out) {
    __shared__ float E0[1024], E1[1024];
    __shared__ float A0[1024], A1[1024];

    const int tid = threadIdx.x;
    const size_t boff = (size_t)blockIdx.x * (2 * NLAB);
    const float* __restrict__ er = em + boff;
    float* __restrict__ orow = out + boff;

    // ================= U1: 256 threads, each owns L8 node p = 255+tid =====
    // Processes its depth-2 subtree (4 leaves -> 2 L9 nodes -> p) privately.
    {
        const int p  = 255 + tid;
        const int l  = 511 + 2 * tid;          // L9 left child
        const int k0 = 1023 + 4 * tid;         // first of 4 leaves

        // top-of-tree emissions (nodes 0..254) loaded cooperatively
        if (tid < 255) { E0[tid] = er[tid]; E1[tid] = er[NLAB + tid]; }

        // own-node emissions -> smem (needed later by warp-mid / D3)
        float ep0 = er[p],     ep1 = er[NLAB + p];
        float el0 = er[l],     el1 = er[NLAB + l];
        float er0 = er[l + 1], er1 = er[NLAB + l + 1];
        E0[p] = ep0; E1[p] = ep1;
        E0[l] = el0; E1[l] = el1;
        E0[l + 1] = er0; E1[l + 1] = er1;

        // leaf emissions
        float le0[4], le1[4];
        #pragma unroll
        for (int j = 0; j < 4; j++) { le0[j] = er[k0 + j]; le1[j] = er[NLAB + k0 + j]; }

        // alphas of the two L9 children (leaf alphas are 0)
        float Al0, Al1, Ar0, Ar1;
        {
            float4 T0 = g_Tup[k0],     T1 = g_Tup[k0 + 1];
            float4 T2 = g_Tup[k0 + 2], T3 = g_Tup[k0 + 3];
            Al0 = lse2(le0[0] + T0.x, le1[0] + T0.y) + lse2(le0[1] + T1.x, le1[1] + T1.y);
            Al1 = lse2(le0[0] + T0.z, le1[0] + T0.w) + lse2(le0[1] + T1.z, le1[1] + T1.w);
            Ar0 = lse2(le0[2] + T2.x, le1[2] + T2.y) + lse2(le0[3] + T3.x, le1[3] + T3.y);
            Ar1 = lse2(le0[2] + T2.z, le1[2] + T2.w) + lse2(le0[3] + T3.z, le1[3] + T3.w);
        }
        A0[l] = Al0; A1[l] = Al1;
        A0[l + 1] = Ar0; A1[l + 1] = Ar1;

        // alpha of p from the two L9 children
        float xl0 = el0 + Al0, xl1 = el1 + Al1;
        float xr0 = er0 + Ar0, xr1 = er1 + Ar1;
        float4 Tl = g_Tup[l], Tr = g_Tup[l + 1];
        A0[p] = lse2(xl0 + Tl.x, xl1 + Tl.y) + lse2(xr0 + Tr.x, xr1 + Tr.y);
        A1[p] = lse2(xl0 + Tl.z, xl1 + Tl.w) + lse2(xr0 + Tr.z, xr1 + Tr.w);
    }
    __syncthreads();   // barrier #1

    // ================= middle: warp 0 only (syncwarp-only section) ========
    if (tid < 32) {
        // ---- U2: thread owns L5 node q=31+tid; subtree L7 -> L6 -> L5
        {
            float af0[4], af1[4];
            #pragma unroll
            for (int j = 0; j < 4; j++) {
                int f = 127 + 4 * tid + j;                 // L7 node
                alpha_children(2 * f + 1, E0, E1, A0, A1, af0[j], af1[j]);
                A0[f] = af0[j]; A1[f] = af1[j];
            }
            float ac0[2], ac1[2];
            #pragma unroll
            for (int jj = 0; jj < 2; jj++) {
                int c  = 63 + 2 * tid + jj;                // L6 node
                int lf = 2 * c + 1;                        // its L7 left child
                float xl0 = E0[lf] + af0[2 * jj],     xl1 = E1[lf] + af1[2 * jj];
                float xr0 = E0[lf + 1] + af0[2 * jj + 1], xr1 = E1[lf + 1] + af1[2 * jj + 1];
                float4 Tl = g_Tup[lf], Tr = g_Tup[lf + 1];
                ac0[jj] = lse2(xl0 + Tl.x, xl1 + Tl.y) + lse2(xr0 + Tr.x, xr1 + Tr.y);
                ac1[jj] = lse2(xl0 + Tl.z, xl1 + Tl.w) + lse2(xr0 + Tr.z, xr1 + Tr.w);
                A0[c] = ac0[jj]; A1[c] = ac1[jj];
            }
            int q  = 31 + tid;
            int lq = 2 * q + 1;
            float xl0 = E0[lq] + ac0[0],     xl1 = E1[lq] + ac1[0];
            float xr0 = E0[lq + 1] + ac0[1], xr1 = E1[lq + 1] + ac1[1];
            float4 Tl = g_Tup[lq], Tr = g_Tup[lq + 1];
            A0[q] = lse2(xl0 + Tl.x, xl1 + Tl.y) + lse2(xr0 + Tr.x, xr1 + Tr.y);
            A1[q] = lse2(xl0 + Tl.z, xl1 + Tl.w) + lse2(xr0 + Tr.z, xr1 + Tr.w);
        }

        // ---- U3: levels 4..0
        #pragma unroll
        for (int lvl = 4; lvl >= 0; --lvl) {
            __syncwarp();
            int base = (1 << lvl) - 1, cnt = 1 << lvl;
            if (tid < cnt) {
                float a0, a1;
                alpha_children(2 * (base + tid) + 1, E0, E1, A0, A1, a0, a1);
                A0[base + tid] = a0; A1[base + tid] = a1;
            }
        }
        __syncwarp();

        // ---- D1: root + levels 1..4 (t = e + beta, stored in place in E)
        if (tid == 0) emit(orow, 0, E0[0] + A0[0], E1[0] + A1[0]);
        #pragma unroll
        for (int lvl = 1; lvl <= 4; ++lvl) {
            __syncwarp();
            int base = (1 << lvl) - 1, cnt = 1 << lvl;
            if (tid < cnt) {
                int n = base + tid, pp = (n - 1) >> 1;
                float t0, t1;
                down_t(n, E0[pp], E1[pp], E0[n], E1[n], t0, t1);
                E0[n] = t0; E1[n] = t1;
                emit(orow, n, t0 + A0[n], t1 + A1[n]);
            }
        }
        __syncwarp();

        // ---- D2: thread owns L5 node q; push t down to L7, emit 7 outputs
        {
            int q = 31 + tid, pp = (q - 1) >> 1;
            float tq0, tq1;
            down_t(q, E0[pp], E1[pp], E0[q], E1[q], tq0, tq1);
            emit(orow, q, tq0 + A0[q], tq1 + A1[q]);
            #pragma unroll
            for (int jj = 0; jj < 2; jj++) {
                int c = 63 + 2 * tid + jj;
                float tc0, tc1;
                down_t(c, tq0, tq1, E0[c], E1[c], tc0, tc1);
                emit(orow, c, tc0 + A0[c], tc1 + A1[c]);
                #pragma unroll
                for (int j2 = 0; j2 < 2; j2++) {
                    int f = 2 * c + 1 + j2;                // L7 node
                    float tf0, tf1;
                    down_t(f, tc0, tc1, E0[f], E1[f], tf0, tf1);
                    E0[f] = tf0; E1[f] = tf1;              // needed by D3
                    emit(orow, f, tf0 + A0[f], tf1 + A1[f]);
                }
            }
        }
    }
    __syncthreads();   // barrier #2

    // ================= D3: 256 threads, push t through own L8 subtree =====
    {
        const int p  = 255 + tid;
        const int pp = 127 + (tid >> 1);       // L7 parent (t final in smem)
        float t0, t1;
        down_t(p, E0[pp], E1[pp], E0[p], E1[p], t0, t1);
        emit(orow, p, t0 + A0[p], t1 + A1[p]);
        const int l = 511 + 2 * tid;
        #pragma unroll
        for (int jj = 0; jj < 2; jj++) {
            int c = l + jj;
            float tc0, tc1;
            down_t(c, t0, t1, E0[c], E1[c], tc0, tc1);
            emit(orow, c, tc0 + A0[c], tc1 + A1[c]);
            #pragma unroll
            for (int j2 = 0; j2 < 2; j2++) {
                int k = 2 * c + 1 + j2;        // leaf (L2-resident re-read)
                float e0 = er[k], e1 = er[NLAB + k];
                float tl0, tl1;
                down_t(k, tc0, tc1, e0, e1, tl0, tl1);
                emit(orow, k, tl0, tl1);       // leaf alpha == 0
            }
        }
    }
}

extern "C" void kernel_launch(void* const* d_in, const int* in_sizes, int n_in,
                              void* d_out, int out_size) {
    const float* em = (const float*)d_in[0];
    const float* tr = (const float*)d_in[1];
    if (n_in >= 2 && in_sizes[0] != NBATCH * 2 * NLAB) {
        em = (const float*)d_in[1];
        tr = (const float*)d_in[0];
    }
    prep_kernel<<<(NLAB + NTHR - 1) / NTHR, NTHR>>>(tr);
    crf_kernel<<<NBATCH, NTHR>>>(em, (float*)d_out);
}

// round 5
// speedup vs baseline: 1.3130x; 1.3130x over previous
#include <cuda_runtime.h>

#define NLAB   2047
#define NBATCH 2048
#define NTHR   256

// Precomputed EXP of compact transition tables (gathered per launch, deterministic).
// eTup[n] = exp(transitions[parent(n), n, :, :])  (message n -> parent)
// eTdn[n] = exp(transitions[n, parent(n), :, :])  (message parent -> n)
// float4: x=exp T[cd=0][cs=0], y=T[0][1], z=T[1][0], w=T[1][1]
__device__ float4 g_eTup[2048];
__device__ float4 g_eTdn[2048];

__global__ void prep_kernel(const float* __restrict__ trans) {
    int n = blockIdx.x * blockDim.x + threadIdx.x;
    if (n >= NLAB) return;
    if (n == 0) {
        g_eTup[0] = make_float4(1.f, 1.f, 1.f, 1.f);
        g_eTdn[0] = make_float4(1.f, 1.f, 1.f, 1.f);
        return;
    }
    int p = (n - 1) >> 1;
    const float4* t4 = reinterpret_cast<const float4*>(trans);
    float4 u = t4[(size_t)p * NLAB + n];   // dst=parent, src=n
    float4 d = t4[(size_t)n * NLAB + p];   // dst=n, src=parent
    g_eTup[n] = make_float4(__expf(u.x), __expf(u.y), __expf(u.z), __expf(u.w));
    g_eTdn[n] = make_float4(__expf(d.x), __expf(d.y), __expf(d.z), __expf(d.w));
}

// Both-destination-class logsumexp for one edge, sharing one exp:
// r0 = log(exp(x0+T00)+exp(x1+T01)), r1 = log(exp(x0+T10)+exp(x1+T11))
__device__ __forceinline__ void lsepair(float x0, float x1, float4 eT,
                                        float& r0, float& r1) {
    float m  = fmaxf(x0, x1);
    float pd = __expf(fminf(x0, x1) - m);   // exp(min-max) <= 1
    bool  f  = (x0 >= x1);                  // x0 is the max?
    float a0 = f ? eT.x : eT.y, b0 = f ? eT.y : eT.x;
    float a1 = f ? eT.z : eT.w, b1 = f ? eT.w : eT.z;
    r0 = m + __logf(fmaf(pd, b0, a0));
    r1 = m + __logf(fmaf(pd, b1, a1));
}

__device__ __forceinline__ float lse2(float u, float v) {
    float m = fmaxf(u, v);
    return m + __logf(1.0f + __expf(fminf(u, v) - m));
}

__device__ __forceinline__ void emit(float* __restrict__ orow, int n,
                                     float s0, float s1) {
    float z = lse2(s0, s1);
    orow[n]        = s0 - z;
    orow[NLAB + n] = s1 - z;
}

// smem: E and A for INTERNAL nodes only (0..1022). E becomes t = e + beta in
// place during the down sweep. Leaves: alpha == 0, emissions read from global.
// 4 * 1024 * 4 B = 16 KB; regs capped to 32 -> 8 CTAs/SM (full occupancy).
__global__ void __launch_bounds__(NTHR, 8) crf_kernel(const float* __restrict__ em,
                                                      float* __restrict__ out) {
    __shared__ float E0[1024], E1[1024];
    __shared__ float A0[1024], A1[1024];

    const int tid = threadIdx.x;
    const size_t boff = (size_t)blockIdx.x * (2 * NLAB);
    const float* __restrict__ er = em + boff;
    float* __restrict__ orow = out + boff;

    // ---- up, leaf level: parents 511..1022 combine their two leaves (alpha=0)
    #pragma unroll
    for (int it = 0; it < 2; ++it) {
        int p = 511 + tid + NTHR * it;
        int k = 2 * p + 1;                        // leaves k, k+1
        float c00, c01, c10, c11;
        lsepair(er[k],     er[NLAB + k],     g_eTup[k],     c00, c01);
        lsepair(er[k + 1], er[NLAB + k + 1], g_eTup[k + 1], c10, c11);
        A0[p] = c00 + c10;
        A1[p] = c01 + c11;
    }
    // internal emissions, coalesced
    for (int i = tid; i < 1023; i += NTHR) { E0[i] = er[i]; E1[i] = er[NLAB + i]; }
    __syncthreads();

    // ---- up, parent levels 8..0
    #pragma unroll
    for (int pl = 8; pl >= 0; --pl) {
        const int base = (1 << pl) - 1;
        const int cnt  = 1 << pl;
        for (int i = tid; i < cnt; i += NTHR) {
            int p = base + i;
            int l = 2 * p + 1;
            float c00, c01, c10, c11;
            lsepair(E0[l] + A0[l],         E1[l] + A1[l],         g_eTup[l],     c00, c01);
            lsepair(E0[l + 1] + A0[l + 1], E1[l + 1] + A1[l + 1], g_eTup[l + 1], c10, c11);
            A0[p] = c00 + c10;
            A1[p] = c01 + c11;
        }
        __syncthreads();
    }

    // ---- root output (beta = 0, t[0] = e[0])
    if (tid == 0) emit(orow, 0, E0[0] + A0[0], E1[0] + A1[0]);

    // ---- down, parent levels 0..8: parent t final in E; compute both
    //      children's t (shared m/pd), store in place, emit children.
    #pragma unroll
    for (int pl = 0; pl <= 8; ++pl) {
        const int base = (1 << pl) - 1;
        const int cnt  = 1 << pl;
        for (int i = tid; i < cnt; i += NTHR) {
            int p = base + i;
            float tp0 = E0[p], tp1 = E1[p];
            float m  = fmaxf(tp0, tp1);
            float pd = __expf(fminf(tp0, tp1) - m);
            bool  f  = (tp0 >= tp1);
            int l = 2 * p + 1;
            #pragma unroll
            for (int j = 0; j < 2; ++j) {
                int n = l + j;
                float4 eT = g_eTdn[n];
                float a0 = f ? eT.x : eT.y, b0 = f ? eT.y : eT.x;
                float a1 = f ? eT.z : eT.w, b1 = f ? eT.w : eT.z;
                float t0 = E0[n] + m + __logf(fmaf(pd, b0, a0));
                float t1 = E1[n] + m + __logf(fmaf(pd, b1, a1));
                E0[n] = t0; E1[n] = t1;
                emit(orow, n, t0 + A0[n], t1 + A1[n]);
            }
        }
        __syncthreads();
    }

    // ---- down, leaf level: parents 511..1022 push t to leaves (alpha = 0)
    #pragma unroll
    for (int it = 0; it < 2; ++it) {
        int p = 511 + tid + NTHR * it;
        float tp0 = E0[p], tp1 = E1[p];
        float m  = fmaxf(tp0, tp1);
        float pd = __expf(fminf(tp0, tp1) - m);
        bool  f  = (tp0 >= tp1);
        int l = 2 * p + 1;
        #pragma unroll
        for (int j = 0; j < 2; ++j) {
            int n = l + j;
            float4 eT = g_eTdn[n];
            float a0 = f ? eT.x : eT.y, b0 = f ? eT.y : eT.x;
            float a1 = f ? eT.z : eT.w, b1 = f ? eT.w : eT.z;
            float t0 = er[n]        + m + __logf(fmaf(pd, b0, a0));
            float t1 = er[NLAB + n] + m + __logf(fmaf(pd, b1, a1));
            emit(orow, n, t0, t1);              // leaf alpha == 0
        }
    }
}

extern "C" void kernel_launch(void* const* d_in, const int* in_sizes, int n_in,
                              void* d_out, int out_size) {
    const float* em = (const float*)d_in[0];
    const float* tr = (const float*)d_in[1];
    if (n_in >= 2 && in_sizes[0] != NBATCH * 2 * NLAB) {
        em = (const float*)d_in[1];
        tr = (const float*)d_in[0];
    }
    prep_kernel<<<(NLAB + NTHR - 1) / NTHR, NTHR>>>(tr);
    crf_kernel<<<NBATCH, NTHR>>>(em, (float*)d_out);
}

// round 6
// speedup vs baseline: 1.4642x; 1.1151x over previous
#include <cuda_runtime.h>

#define NLAB   2047
#define NBATCH 2048
#define NTHR   256

// Precomputed EXP of compact transition tables (gathered per launch, deterministic).
// eTup[n] = exp(transitions[parent(n), n, :, :])  (message n -> parent)
// eTdn[n] = exp(transitions[n, parent(n), :, :])  (message parent -> n)
__device__ float4 g_eTup[2048];
__device__ float4 g_eTdn[2048];

__global__ void prep_kernel(const float* __restrict__ trans) {
    int n = blockIdx.x * blockDim.x + threadIdx.x;
    if (n >= NLAB) return;
    if (n == 0) {
        g_eTup[0] = make_float4(1.f, 1.f, 1.f, 1.f);
        g_eTdn[0] = make_float4(1.f, 1.f, 1.f, 1.f);
        return;
    }
    int p = (n - 1) >> 1;
    const float4* t4 = reinterpret_cast<const float4*>(trans);
    float4 u = t4[(size_t)p * NLAB + n];   // dst=parent, src=n
    float4 d = t4[(size_t)n * NLAB + p];   // dst=n, src=parent
    g_eTup[n] = make_float4(__expf(u.x), __expf(u.y), __expf(u.z), __expf(u.w));
    g_eTdn[n] = make_float4(__expf(d.x), __expf(d.y), __expf(d.z), __expf(d.w));
}

// Both-destination-class logsumexp for one edge, sharing one exp.
__device__ __forceinline__ void lsepair(float x0, float x1, float4 eT,
                                        float& r0, float& r1) {
    float m  = fmaxf(x0, x1);
    float pd = __expf(fminf(x0, x1) - m);
    bool  f  = (x0 >= x1);
    float a0 = f ? eT.x : eT.y, b0 = f ? eT.y : eT.x;
    float a1 = f ? eT.z : eT.w, b1 = f ? eT.w : eT.z;
    r0 = m + __logf(fmaf(pd, b0, a0));
    r1 = m + __logf(fmaf(pd, b1, a1));
}

__device__ __forceinline__ float lse2(float u, float v) {
    float m = fmaxf(u, v);
    return m + __logf(1.0f + __expf(fminf(u, v) - m));
}

__device__ __forceinline__ void emit(float* __restrict__ orow, int n,
                                     float s0, float s1) {
    float z = lse2(s0, s1);
    orow[n]        = s0 - z;
    orow[NLAB + n] = s1 - z;
}

// TWO batch rows per CTA. smem holds E and A (float2: class0/class1 packed)
// for internal nodes of both rows: 2 rows * 2 arrays * 1024 * 8B = 32 KB.
// E becomes t = e + beta in place during the down sweep. Leaves: alpha == 0,
// emissions re-read from global (L1/L2 hit). 5 CTAs/SM.
__global__ void __launch_bounds__(NTHR, 5) crf_kernel(const float* __restrict__ em,
                                                      float* __restrict__ out) {
    __shared__ float2 E[2][1024];
    __shared__ float2 A[2][1024];

    const int tid = threadIdx.x;
    const size_t b0 = (size_t)(2 * blockIdx.x) * (2 * NLAB);
    const float* __restrict__ er0 = em + b0;
    const float* __restrict__ er1 = er0 + 2 * NLAB;
    float* __restrict__ o0 = out + b0;
    float* __restrict__ o1 = o0 + 2 * NLAB;

    // ---- up, leaf level: parents 511..1022 combine their two leaves (alpha=0)
    #pragma unroll
    for (int it = 0; it < 2; ++it) {
        int p = 511 + tid + NTHR * it;
        int k = 2 * p + 1;                       // leaves k, k+1
        float4 Tl = g_eTup[k], Tr = g_eTup[k + 1];
        {
            float c00, c01, c10, c11;
            lsepair(er0[k],     er0[NLAB + k],     Tl, c00, c01);
            lsepair(er0[k + 1], er0[NLAB + k + 1], Tr, c10, c11);
            A[0][p] = make_float2(c00 + c10, c01 + c11);
        }
        {
            float c00, c01, c10, c11;
            lsepair(er1[k],     er1[NLAB + k],     Tl, c00, c01);
            lsepair(er1[k + 1], er1[NLAB + k + 1], Tr, c10, c11);
            A[1][p] = make_float2(c00 + c10, c01 + c11);
        }
    }
    // internal emissions, coalesced
    for (int i = tid; i < 1023; i += NTHR) {
        E[0][i] = make_float2(er0[i], er0[NLAB + i]);
        E[1][i] = make_float2(er1[i], er1[NLAB + i]);
    }
    __syncthreads();

    // ---- up, parent levels 8..0
    #pragma unroll
    for (int pl = 8; pl >= 0; --pl) {
        const int base = (1 << pl) - 1;
        const int cnt  = 1 << pl;
        for (int i = tid; i < cnt; i += NTHR) {
            int p = base + i;
            int l = 2 * p + 1;
            float4 Tl = g_eTup[l], Tr = g_eTup[l + 1];
            #pragma unroll
            for (int r = 0; r < 2; ++r) {
                float2 el = E[r][l],     al = A[r][l];
                float2 ec = E[r][l + 1], ac = A[r][l + 1];
                float c00, c01, c10, c11;
                lsepair(el.x + al.x, el.y + al.y, Tl, c00, c01);
                lsepair(ec.x + ac.x, ec.y + ac.y, Tr, c10, c11);
                A[r][p] = make_float2(c00 + c10, c01 + c11);
            }
        }
        __syncthreads();
    }

    // ---- root outputs (beta = 0, t[0] = e[0])
    if (tid == 0) {
        { float2 e = E[0][0], a = A[0][0]; emit(o0, 0, e.x + a.x, e.y + a.y); }
        { float2 e = E[1][0], a = A[1][0]; emit(o1, 0, e.x + a.x, e.y + a.y); }
    }

    // ---- down, parent levels 0..8: parent t final in E; compute both
    //      children's t (shared m/pd), store in place, emit children.
    #pragma unroll
    for (int pl = 0; pl <= 8; ++pl) {
        const int base = (1 << pl) - 1;
        const int cnt  = 1 << pl;
        for (int i = tid; i < cnt; i += NTHR) {
            int p = base + i;
            int l = 2 * p + 1;
            float4 TL = g_eTdn[l], TR = g_eTdn[l + 1];
            #pragma unroll
            for (int r = 0; r < 2; ++r) {
                float* __restrict__ orow = r ? o1 : o0;
                float2 tp = E[r][p];
                float m  = fmaxf(tp.x, tp.y);
                float pd = __expf(fminf(tp.x, tp.y) - m);
                bool  f  = (tp.x >= tp.y);
                #pragma unroll
                for (int j = 0; j < 2; ++j) {
                    int n = l + j;
                    float4 eT = j ? TR : TL;
                    float a0 = f ? eT.x : eT.y, b0 = f ? eT.y : eT.x;
                    float a1 = f ? eT.z : eT.w, b1 = f ? eT.w : eT.z;
                    float2 en = E[r][n], an = A[r][n];
                    float t0 = en.x + m + __logf(fmaf(pd, b0, a0));
                    float t1 = en.y + m + __logf(fmaf(pd, b1, a1));
                    E[r][n] = make_float2(t0, t1);
                    emit(orow, n, t0 + an.x, t1 + an.y);
                }
            }
        }
        __syncthreads();
    }

    // ---- down, leaf level: parents 511..1022 push t to leaves (alpha = 0)
    #pragma unroll
    for (int it = 0; it < 2; ++it) {
        int p = 511 + tid + NTHR * it;
        int l = 2 * p + 1;
        float4 TL = g_eTdn[l], TR = g_eTdn[l + 1];
        #pragma unroll
        for (int r = 0; r < 2; ++r) {
            const float* __restrict__ er = r ? er1 : er0;
            float* __restrict__ orow     = r ? o1  : o0;
            float2 tp = E[r][p];
            float m  = fmaxf(tp.x, tp.y);
            float pd = __expf(fminf(tp.x, tp.y) - m);
            bool  f  = (tp.x >= tp.y);
            #pragma unroll
            for (int j = 0; j < 2; ++j) {
                int n = l + j;
                float4 eT = j ? TR : TL;
                float a0 = f ? eT.x : eT.y, b0 = f ? eT.y : eT.x;
                float a1 = f ? eT.z : eT.w, b1 = f ? eT.w : eT.z;
                float t0 = er[n]        + m + __logf(fmaf(pd, b0, a0));
                float t1 = er[NLAB + n] + m + __logf(fmaf(pd, b1, a1));
                emit(orow, n, t0, t1);          // leaf alpha == 0
            }
        }
    }
}

extern "C" void kernel_launch(void* const* d_in, const int* in_sizes, int n_in,
                              void* d_out, int out_size) {
    const float* em = (const float*)d_in[0];
    const float* tr = (const float*)d_in[1];
    if (n_in >= 2 && in_sizes[0] != NBATCH * 2 * NLAB) {
        em = (const float*)d_in[1];
        tr = (const float*)d_in[0];
    }
    prep_kernel<<<(NLAB + NTHR - 1) / NTHR, NTHR>>>(tr);
    crf_kernel<<<NBATCH / 2, NTHR>>>(em, (float*)d_out);
}